// round 1
// baseline (speedup 1.0000x reference)
#include <cuda_runtime.h>

#define BN 4
#define NN 2048
#define IND 128
#define HIDD 64
#define NHEADS 4

// ---------------- scratch (__device__ globals; no allocations allowed) ----------------
__device__ float g_hcat[BN * NN * 256];   // layer-1 per-head projections, interleaved [B][N][H*64]
__device__ float g_att1[BN * NN * 256];   // layer-1 attention output (concat heads) = layer-2 input
__device__ float g_h2[BN * NN * 64];      // layer-2 projection

// per-node exp factors: exp(s), exp(0.2 s), exp(t), exp(0.2 t)
__device__ float g_Es1[NHEADS * BN * NN];
__device__ float g_Fs1[NHEADS * BN * NN];
__device__ float g_Et1[NHEADS * BN * NN];
__device__ float g_Ft1[NHEADS * BN * NN];
__device__ float g_Es2[BN * NN];
__device__ float g_Fs2[BN * NN];
__device__ float g_Et2[BN * NN];
__device__ float g_Ft2[BN * NN];

__device__ __forceinline__ float warp_sum(float v) {
#pragma unroll
    for (int o = 16; o > 0; o >>= 1) v += __shfl_xor_sync(0xffffffffu, v, o);
    return v;
}

// ---------------- proj1: hcat = x @ W_heads (all 4 heads), plus s/t exp factors ----------------
// 16 rows per block, 256 threads (thread = (head h, dim d)). W reused across 16 rows.
__global__ void proj1_kernel(const float* __restrict__ x,
                             const float* __restrict__ W,
                             const float* __restrict__ a) {
    __shared__ float xs[16][136];            // 128 + pad, 544B row pitch (16B aligned)
    __shared__ float rs[16][8], rt[16][8];
    const int row0 = blockIdx.x * 16;
    const int tid = threadIdx.x;

#pragma unroll
    for (int u = 0; u < 2; ++u) {
        int idx = tid + u * 256;             // 512 float4 total
        int r = idx >> 5, c = (idx & 31) * 4;
        *(float4*)&xs[r][c] = *(const float4*)&x[(size_t)(row0 + r) * IND + c];
    }
    __syncthreads();

    const int h = tid >> 6, d = tid & 63;
    const float* Wc = W + (size_t)(h * IND) * HIDD + d;
    float acc[16];
#pragma unroll
    for (int r = 0; r < 16; ++r) acc[r] = 0.f;
#pragma unroll 4
    for (int i = 0; i < IND; ++i) {
        float wv = Wc[(size_t)i * HIDD];
#pragma unroll
        for (int r = 0; r < 16; ++r) acc[r] += xs[r][i] * wv;
    }

    const float a1 = a[h * 128 + d];
    const float a2 = a[h * 128 + 64 + d];
    const int warp = tid >> 5, lane = tid & 31;
#pragma unroll
    for (int r = 0; r < 16; ++r) {
        g_hcat[(size_t)(row0 + r) * 256 + tid] = acc[r];
        float sp = warp_sum(acc[r] * a1);
        float tp = warp_sum(acc[r] * a2);
        if (lane == 0) { rs[r][warp] = sp; rt[r][warp] = tp; }
    }
    __syncthreads();
    if ((tid & 63) == 0) {
#pragma unroll
        for (int r = 0; r < 16; ++r) {
            float S = rs[r][2 * h] + rs[r][2 * h + 1];
            float T = rt[r][2 * h] + rt[r][2 * h + 1];
            size_t idx = (size_t)h * (BN * NN) + row0 + r;
            g_Es1[idx] = expf(S);
            g_Fs1[idx] = expf(0.2f * S);
            g_Et1[idx] = expf(T);
            g_Ft1[idx] = expf(0.2f * T);
        }
    }
}

// ---------------- proj2: h2 = att1 @ W_out, plus s/t exp factors ----------------
__global__ void proj2_kernel(const float* __restrict__ Wout,
                             const float* __restrict__ aout) {
    __shared__ float ys[16][260];            // 256 + pad, 1040B pitch (16B aligned)
    __shared__ float part[4][16][64];
    __shared__ float rs[16][2], rt[16][2];
    const int row0 = blockIdx.x * 16;
    const int tid = threadIdx.x;

#pragma unroll
    for (int u = 0; u < 4; ++u) {
        int idx = tid + u * 256;             // 1024 float4 total
        int r = idx >> 6, c = (idx & 63) * 4;
        *(float4*)&ys[r][c] = *(const float4*)&g_att1[(size_t)(row0 + r) * 256 + c];
    }
    __syncthreads();

    const int p = tid >> 6, d = tid & 63;
    float acc[16];
#pragma unroll
    for (int r = 0; r < 16; ++r) acc[r] = 0.f;
#pragma unroll 4
    for (int i = 0; i < 64; ++i) {
        float wv = Wout[(size_t)(p * 64 + i) * 64 + d];
#pragma unroll
        for (int r = 0; r < 16; ++r) acc[r] += ys[r][p * 64 + i] * wv;
    }
#pragma unroll
    for (int r = 0; r < 16; ++r) part[p][r][d] = acc[r];
    __syncthreads();

    if (p == 0) {
        const float a1 = aout[d], a2 = aout[64 + d];
        const int warp = tid >> 5, lane = tid & 31;
#pragma unroll
        for (int r = 0; r < 16; ++r) {
            float v = part[0][r][d] + part[1][r][d] + part[2][r][d] + part[3][r][d];
            g_h2[(size_t)(row0 + r) * 64 + d] = v;
            float sp = warp_sum(v * a1);
            float tp = warp_sum(v * a2);
            if (lane == 0) { rs[r][warp] = sp; rt[r][warp] = tp; }
        }
    }
    __syncthreads();
    if (tid < 16) {
        float S = rs[tid][0] + rs[tid][1];
        float T = rt[tid][0] + rt[tid][1];
        size_t idx = (size_t)(row0 + tid);
        g_Es2[idx] = expf(S);
        g_Fs2[idx] = expf(0.2f * S);
        g_Et2[idx] = expf(T);
        g_Ft2[idx] = expf(0.2f * T);
    }
}

// ---------------- attention: out_i = sum_j w_ij h_j / sum_j w_ij ----------------
// w_ij = adj_ij * (Es_i*Et_j > 1 ? Es_i*Et_j : Fs_i*Ft_j)   [separable leaky-relu-exp]
// R rows per block, 64-col j tiles. 256 threads.
// L==1: hcat(stride 256) -> g_att1 ;  L==2: g_h2(stride 64) -> external out
template <int R, int L>
__global__ void attn_kernel(const int* __restrict__ adj, float* __restrict__ out_ext) {
    constexpr int HS = (L == 1) ? 256 : 64;  // h row stride
    constexpr int OS = (L == 1) ? 256 : 64;  // out row stride
    const float* __restrict__ hsrc = (L == 1) ? g_hcat : g_h2;
    const float* __restrict__ Es = (L == 1) ? g_Es1 : g_Es2;
    const float* __restrict__ Fs = (L == 1) ? g_Fs1 : g_Fs2;
    const float* __restrict__ Et = (L == 1) ? g_Et1 : g_Et2;
    const float* __restrict__ Ft = (L == 1) ? g_Ft1 : g_Ft2;
    float* __restrict__ out = (L == 1) ? g_att1 : out_ext;

    __shared__ float h_sh[64][68];
    __shared__ float w_sh[R][68];
    __shared__ float Es_sh[R], Fs_sh[R], den_sh[R];

    const int tid = threadIdx.x;
    const int b = blockIdx.z, head = blockIdx.y;
    const int i0 = blockIdx.x * R;
    const size_t ebase = ((size_t)head * BN + b) * NN;
    const float* hb = hsrc + ((size_t)b * NN) * HS + head * 64;
    float* ob = out + ((size_t)b * NN) * OS + head * 64;
    const int* adjb = adj + (size_t)b * NN * NN;

    if (tid < R) {
        Es_sh[tid] = Es[ebase + i0 + tid];
        Fs_sh[tid] = Fs[ebase + i0 + tid];
        den_sh[tid] = 0.f;
    }
    __syncthreads();

    constexpr int RT = R / 4;                 // rows/thread (w phase) == dims/thread (gemm phase)
    const int jl = tid & 63, rg = tid >> 6;
    float EsR[RT], FsR[RT], denp[RT];
#pragma unroll
    for (int k = 0; k < RT; ++k) {
        EsR[k] = Es_sh[rg * RT + k];
        FsR[k] = Fs_sh[rg * RT + k];
        denp[k] = 0.f;
    }

    constexpr int LPR = 64 / RT;              // gemm lanes per row
    const int gi = tid / LPR;
    const int gd0 = (tid % LPR) * RT;
    float acc[RT];
#pragma unroll
    for (int k = 0; k < RT; ++k) acc[k] = 0.f;

    for (int j0 = 0; j0 < NN; j0 += 64) {
        // load 64x64 h tile
#pragma unroll
        for (int u = 0; u < 4; ++u) {
            int idx = tid + u * 256;
            int jr = idx >> 4, c = (idx & 15) * 4;
            *(float4*)&h_sh[jr][c] = *(const float4*)&hb[(size_t)(j0 + jr) * HS + c];
        }
        // compute w tile + accumulate denominator partials
        const float Etv = Et[ebase + j0 + jl];
        const float Ftv = Ft[ebase + j0 + jl];
        const int* arow = adjb + (size_t)(i0 + rg * RT) * NN + j0 + jl;
#pragma unroll
        for (int k = 0; k < RT; ++k) {
            int av = arow[(size_t)k * NN];
            float p1 = EsR[k] * Etv;               // exp(s+t)
            float w = (p1 > 1.f) ? p1 : FsR[k] * Ftv;  // s+t<=0 -> exp(0.2(s+t))
            w = av ? w : 0.f;
            w_sh[rg * RT + k][jl] = w;
            denp[k] += w;
        }
        __syncthreads();
        // micro-GEMM: acc[gd0..] += w_sh[gi][:] * h_sh[:][gd0..]
#pragma unroll 8
        for (int jt = 0; jt < 64; ++jt) {
            float wv = w_sh[gi][jt];
            const float* hr = &h_sh[jt][gd0];
#pragma unroll
            for (int k = 0; k < RT; ++k) acc[k] += wv * hr[k];
        }
        __syncthreads();
    }

#pragma unroll
    for (int k = 0; k < RT; ++k) atomicAdd(&den_sh[rg * RT + k], denp[k]);
    __syncthreads();

    float dv = den_sh[gi];
    float inv = (dv > 0.f) ? 1.0f / dv : 0.f;     // all-masked row can't occur with random adj
#pragma unroll
    for (int k = 0; k < RT; ++k)
        ob[(size_t)(i0 + gi) * OS + gd0 + k] = acc[k] * inv;
}

extern "C" void kernel_launch(void* const* d_in, const int* in_sizes, int n_in,
                              void* d_out, int out_size) {
    const float* x   = (const float*)d_in[0];
    const int*   adj = (const int*)  d_in[1];
    const float* Wh  = (const float*)d_in[2];
    const float* ah  = (const float*)d_in[3];
    const float* Wo  = (const float*)d_in[4];
    const float* ao  = (const float*)d_in[5];
    float* out = (float*)d_out;

    proj1_kernel<<<BN * NN / 16, 256>>>(x, Wh, ah);
    attn_kernel<32, 1><<<dim3(NN / 32, NHEADS, BN), 256>>>(adj, nullptr);
    proj2_kernel<<<BN * NN / 16, 256>>>(Wo, ao);
    attn_kernel<16, 2><<<dim3(NN / 16, 1, BN), 256>>>(adj, out);
}

// round 2
// speedup vs baseline: 3.4834x; 3.4834x over previous
#include <cuda_runtime.h>

#define BN 4
#define NN 2048
#define IND 128
#define NHEADS 4

// ---------------- scratch ----------------
__device__ float g_hcat[BN * NN * 256];
__device__ float g_att1[BN * NN * 256];
__device__ float g_h2[BN * NN * 64];
__device__ float g_num2[2 * BN * NN * 64];   // layer-2 split-K partial numerators
__device__ float g_den2[2 * BN * NN];        // layer-2 split-K partial denominators

__device__ float g_Es1[NHEADS * BN * NN];
__device__ float g_Fs1[NHEADS * BN * NN];
__device__ float g_Et1[NHEADS * BN * NN];
__device__ float g_Ft1[NHEADS * BN * NN];
__device__ float g_Es2[BN * NN];
__device__ float g_Fs2[BN * NN];
__device__ float g_Et2[BN * NN];
__device__ float g_Ft2[BN * NN];

__device__ __forceinline__ float warp_sum(float v) {
#pragma unroll
    for (int o = 16; o > 0; o >>= 1) v += __shfl_xor_sync(0xffffffffu, v, o);
    return v;
}

// ---------------- proj1: hcat = x @ W_heads + per-node exp factors ----------------
__global__ void proj1_kernel(const float* __restrict__ x,
                             const float* __restrict__ W,
                             const float* __restrict__ a) {
    __shared__ float xs[16][136];
    __shared__ float rs[16][8], rt[16][8];
    const int row0 = blockIdx.x * 16;
    const int tid = threadIdx.x;

#pragma unroll
    for (int u = 0; u < 2; ++u) {
        int idx = tid + u * 256;
        int r = idx >> 5, c = (idx & 31) * 4;
        *(float4*)&xs[r][c] = *(const float4*)&x[(size_t)(row0 + r) * IND + c];
    }
    __syncthreads();

    const int h = tid >> 6, d = tid & 63;
    const float* Wc = W + (size_t)(h * IND) * 64 + d;
    float acc[16];
#pragma unroll
    for (int r = 0; r < 16; ++r) acc[r] = 0.f;
#pragma unroll 4
    for (int i = 0; i < IND; ++i) {
        float wv = Wc[(size_t)i * 64];
#pragma unroll
        for (int r = 0; r < 16; ++r) acc[r] += xs[r][i] * wv;
    }

    const float a1 = a[h * 128 + d];
    const float a2 = a[h * 128 + 64 + d];
    const int warp = tid >> 5, lane = tid & 31;
#pragma unroll
    for (int r = 0; r < 16; ++r) {
        g_hcat[(size_t)(row0 + r) * 256 + tid] = acc[r];
        float sp = warp_sum(acc[r] * a1);
        float tp = warp_sum(acc[r] * a2);
        if (lane == 0) { rs[r][warp] = sp; rt[r][warp] = tp; }
    }
    __syncthreads();
    if ((tid & 63) == 0) {
#pragma unroll
        for (int r = 0; r < 16; ++r) {
            float S = rs[r][2 * h] + rs[r][2 * h + 1];
            float T = rt[r][2 * h] + rt[r][2 * h + 1];
            size_t idx = (size_t)h * (BN * NN) + row0 + r;
            g_Es1[idx] = expf(S);
            g_Fs1[idx] = expf(0.2f * S);
            g_Et1[idx] = expf(T);
            g_Ft1[idx] = expf(0.2f * T);
        }
    }
}

// ---------------- proj2: h2 = att1 @ W_out + per-node exp factors ----------------
__global__ void proj2_kernel(const float* __restrict__ Wout,
                             const float* __restrict__ aout) {
    __shared__ float ys[16][260];
    __shared__ float part[4][16][64];
    __shared__ float rs[16][2], rt[16][2];
    const int row0 = blockIdx.x * 16;
    const int tid = threadIdx.x;

#pragma unroll
    for (int u = 0; u < 4; ++u) {
        int idx = tid + u * 256;
        int r = idx >> 6, c = (idx & 63) * 4;
        *(float4*)&ys[r][c] = *(const float4*)&g_att1[(size_t)(row0 + r) * 256 + c];
    }
    __syncthreads();

    const int p = tid >> 6, d = tid & 63;
    float acc[16];
#pragma unroll
    for (int r = 0; r < 16; ++r) acc[r] = 0.f;
#pragma unroll 4
    for (int i = 0; i < 64; ++i) {
        float wv = Wout[(size_t)(p * 64 + i) * 64 + d];
#pragma unroll
        for (int r = 0; r < 16; ++r) acc[r] += ys[r][p * 64 + i] * wv;
    }
#pragma unroll
    for (int r = 0; r < 16; ++r) part[p][r][d] = acc[r];
    __syncthreads();

    if (p == 0) {
        const float a1 = aout[d], a2 = aout[64 + d];
        const int warp = tid >> 5, lane = tid & 31;
#pragma unroll
        for (int r = 0; r < 16; ++r) {
            float v = part[0][r][d] + part[1][r][d] + part[2][r][d] + part[3][r][d];
            g_h2[(size_t)(row0 + r) * 64 + d] = v;
            float sp = warp_sum(v * a1);
            float tp = warp_sum(v * a2);
            if (lane == 0) { rs[r][warp] = sp; rt[r][warp] = tp; }
        }
    }
    __syncthreads();
    if (tid < 16) {
        float S = rs[tid][0] + rs[tid][1];
        float T = rt[tid][0] + rt[tid][1];
        size_t idx = (size_t)(row0 + tid);
        g_Es2[idx] = expf(S);
        g_Fs2[idx] = expf(0.2f * S);
        g_Et2[idx] = expf(T);
        g_Ft2[idx] = expf(0.2f * T);
    }
}

// ---------------- attention, register-blocked ----------------
// w_ij = adj_ij * (Es_i*Et_j > 1 ? Es_i*Et_j : Fs_i*Ft_j)
// Block: ROWS x 64 dims, j tiled by 32. 256 threads.
// GEMM mapping: rg=tid>>4 owns TR rows, dg=tid&15 owns 4 dims (thread tile TR x 4).
// w stored transposed w_sh[j][row] so both operands are LDS.128.
template <int ROWS, int TR, int L, int SPL>
__global__ void __launch_bounds__(256)
attn_k(const int* __restrict__ adj, float* __restrict__ out_unused) {
    constexpr int JT = 32;
    constexpr int HS = (L == 1) ? 256 : 64;
    constexpr int WR = ROWS / 32;           // rows/thread in w phase
    const float* __restrict__ hsrc = (L == 1) ? g_hcat : g_h2;
    const float* __restrict__ Es = (L == 1) ? g_Es1 : g_Es2;
    const float* __restrict__ Fs = (L == 1) ? g_Fs1 : g_Fs2;
    const float* __restrict__ Et = (L == 1) ? g_Et1 : g_Et2;
    const float* __restrict__ Ft = (L == 1) ? g_Ft1 : g_Ft2;

    __shared__ float h_sh[JT][64];
    __shared__ float w_sh[JT][ROWS + 4];
    __shared__ float Es_sh[ROWS], Fs_sh[ROWS], den_sh[ROWS];

    const int tid = threadIdx.x;
    const int b = blockIdx.z;
    const int head = (L == 1) ? blockIdx.y : 0;
    const int split = (L == 1) ? 0 : blockIdx.y;
    const int i0 = blockIdx.x * ROWS;
    const size_t ebase = ((L == 1) ? ((size_t)head * BN + b) : (size_t)b) * NN;
    const float* hb = hsrc + (size_t)b * NN * HS + head * 64;
    const int* adjb = adj + (size_t)b * NN * NN;

    for (int r = tid; r < ROWS; r += 256) {
        Es_sh[r] = Es[ebase + i0 + r];
        Fs_sh[r] = Fs[ebase + i0 + r];
        den_sh[r] = 0.f;
    }
    __syncthreads();

    // w-phase ids: c4 = col group (4 cols), rw = row group (WR rows)
    const int c4 = tid & 7;
    const int rw = tid >> 3;
    float esr[WR], fsr[WR], denp[WR];
#pragma unroll
    for (int k = 0; k < WR; ++k) {
        esr[k] = Es_sh[rw * WR + k];
        fsr[k] = Fs_sh[rw * WR + k];
        denp[k] = 0.f;
    }

    const int rg = tid >> 4;
    const int dg = tid & 15;
    float acc[TR][4];
#pragma unroll
    for (int k = 0; k < TR; ++k)
#pragma unroll
        for (int c = 0; c < 4; ++c) acc[k][c] = 0.f;

    const int j_begin = split * (NN / SPL);
    for (int j0 = j_begin; j0 < j_begin + NN / SPL; j0 += JT) {
        // load h tile [32][64]
#pragma unroll
        for (int u = 0; u < 2; ++u) {
            int idx = tid + u * 256;
            int jr = idx >> 4, c = (idx & 15) * 4;
            *(float4*)&h_sh[jr][c] = *(const float4*)&hb[(size_t)(j0 + jr) * HS + c];
        }
        // compute w tile (transposed store)
        float4 Et4 = *(const float4*)&Et[ebase + j0 + c4 * 4];
        float4 Ft4 = *(const float4*)&Ft[ebase + j0 + c4 * 4];
        float wv[4][WR];
#pragma unroll
        for (int k = 0; k < WR; ++k) {
            int row = rw * WR + k;
            int4 av = *(const int4*)&adjb[(size_t)(i0 + row) * NN + j0 + c4 * 4];
            float p, w0, w1, w2, w3;
            p = esr[k] * Et4.x; w0 = (p > 1.f) ? p : fsr[k] * Ft4.x; w0 = av.x ? w0 : 0.f;
            p = esr[k] * Et4.y; w1 = (p > 1.f) ? p : fsr[k] * Ft4.y; w1 = av.y ? w1 : 0.f;
            p = esr[k] * Et4.z; w2 = (p > 1.f) ? p : fsr[k] * Ft4.z; w2 = av.z ? w2 : 0.f;
            p = esr[k] * Et4.w; w3 = (p > 1.f) ? p : fsr[k] * Ft4.w; w3 = av.w ? w3 : 0.f;
            wv[0][k] = w0; wv[1][k] = w1; wv[2][k] = w2; wv[3][k] = w3;
            denp[k] += (w0 + w1) + (w2 + w3);
        }
#pragma unroll
        for (int cc = 0; cc < 4; ++cc) {
            if constexpr (WR == 4) {
                *(float4*)&w_sh[c4 * 4 + cc][rw * 4] =
                    make_float4(wv[cc][0], wv[cc][1], wv[cc][2], wv[cc][3]);
            } else {
                *(float2*)&w_sh[c4 * 4 + cc][rw * 2] = make_float2(wv[cc][0], wv[cc][1]);
            }
        }
        __syncthreads();
        // register-blocked micro-GEMM
#pragma unroll 4
        for (int jt = 0; jt < JT; ++jt) {
            float4 hv = *(const float4*)&h_sh[jt][dg * 4];
            float wr[TR];
#pragma unroll
            for (int k = 0; k < TR; k += 4) {
                float4 w4 = *(const float4*)&w_sh[jt][rg * TR + k];
                wr[k] = w4.x; wr[k + 1] = w4.y; wr[k + 2] = w4.z; wr[k + 3] = w4.w;
            }
#pragma unroll
            for (int k = 0; k < TR; ++k) {
                acc[k][0] += wr[k] * hv.x;
                acc[k][1] += wr[k] * hv.y;
                acc[k][2] += wr[k] * hv.z;
                acc[k][3] += wr[k] * hv.w;
            }
        }
        __syncthreads();
    }

#pragma unroll
    for (int k = 0; k < WR; ++k) atomicAdd(&den_sh[rw * WR + k], denp[k]);
    __syncthreads();

    if constexpr (L == 1) {
#pragma unroll
        for (int k = 0; k < TR; ++k) {
            int row = i0 + rg * TR + k;
            float inv = 1.0f / den_sh[rg * TR + k];
            *(float4*)&g_att1[((size_t)b * NN + row) * 256 + head * 64 + dg * 4] =
                make_float4(acc[k][0] * inv, acc[k][1] * inv, acc[k][2] * inv, acc[k][3] * inv);
        }
    } else {
        float* nump = g_num2 + ((size_t)split * BN + b) * NN * 64;
#pragma unroll
        for (int k = 0; k < TR; ++k) {
            int row = i0 + rg * TR + k;
            *(float4*)&nump[(size_t)row * 64 + dg * 4] =
                make_float4(acc[k][0], acc[k][1], acc[k][2], acc[k][3]);
        }
        if (tid < ROWS)
            g_den2[((size_t)split * BN + b) * NN + i0 + tid] = den_sh[tid];
    }
}

// ---------------- layer-2 split-K combine ----------------
__global__ void combine2_kernel(float* __restrict__ out) {
    size_t idx = (size_t)blockIdx.x * 256 + threadIdx.x;  // BN*NN*16 float4s
    size_t row = idx >> 4;
    int c = (int)(idx & 15) * 4;
    float d = g_den2[row] + g_den2[(size_t)BN * NN + row];
    float inv = 1.0f / d;
    float4 n0 = *(const float4*)&g_num2[row * 64 + c];
    float4 n1 = *(const float4*)&g_num2[(size_t)BN * NN * 64 + row * 64 + c];
    *(float4*)&out[row * 64 + c] =
        make_float4((n0.x + n1.x) * inv, (n0.y + n1.y) * inv,
                    (n0.z + n1.z) * inv, (n0.w + n1.w) * inv);
}

extern "C" void kernel_launch(void* const* d_in, const int* in_sizes, int n_in,
                              void* d_out, int out_size) {
    const float* x   = (const float*)d_in[0];
    const int*   adj = (const int*)  d_in[1];
    const float* Wh  = (const float*)d_in[2];
    const float* ah  = (const float*)d_in[3];
    const float* Wo  = (const float*)d_in[4];
    const float* ao  = (const float*)d_in[5];
    float* out = (float*)d_out;

    proj1_kernel<<<BN * NN / 16, 256>>>(x, Wh, ah);
    attn_k<128, 8, 1, 1><<<dim3(NN / 128, NHEADS, BN), 256>>>(adj, nullptr);
    proj2_kernel<<<BN * NN / 16, 256>>>(Wo, ao);
    attn_k<64, 4, 2, 2><<<dim3(NN / 64, 2, BN), 256>>>(adj, nullptr);
    combine2_kernel<<<BN * NN * 16 / 256, 256>>>(out);
}

// round 4
// speedup vs baseline: 5.9064x; 1.6956x over previous
#include <cuda_runtime.h>
#include <cstdint>

#define BN 4
#define NN 2048
#define IND 128
#define NHEADS 4

// ---------------- scratch ----------------
__device__ float g_hcat[(size_t)BN * NN * 256];     // layer-1 h (tf32-rounded), [b][n][h*64+d]
__device__ float g_att1[(size_t)BN * NN * 256];     // layer-1 attention out (fp32)
__device__ float g_h2[(size_t)BN * NN * 64];        // layer-2 h (tf32-rounded)
__device__ float g_num2[(size_t)4 * BN * NN * 64];  // layer-2 split-K numerators
__device__ float g_den2[(size_t)4 * BN * NN];
__device__ uint32_t g_adjp[(size_t)BN * NN * (NN / 32)];  // bit-packed adjacency

__device__ float g_Es1[NHEADS * BN * NN];
__device__ float g_Fs1[NHEADS * BN * NN];
__device__ float g_Et1[NHEADS * BN * NN];
__device__ float g_Ft1[NHEADS * BN * NN];
__device__ float g_Es2[BN * NN];
__device__ float g_Fs2[BN * NN];
__device__ float g_Et2[BN * NN];
__device__ float g_Ft2[BN * NN];

__device__ __forceinline__ float tf32r(float x) {
    uint32_t v;
    asm("cvt.rna.tf32.f32 %0, %1;" : "=r"(v) : "f"(x));
    return __uint_as_float(v);
}
__device__ __forceinline__ float warp_sum(float v) {
#pragma unroll
    for (int o = 16; o > 0; o >>= 1) v += __shfl_xor_sync(0xffffffffu, v, o);
    return v;
}
__device__ __forceinline__ void mma_tf32(float* c, uint32_t a0, uint32_t a1, uint32_t a2,
                                         uint32_t a3, uint32_t b0, uint32_t b1) {
    asm volatile(
        "mma.sync.aligned.m16n8k8.row.col.f32.tf32.tf32.f32 "
        "{%0,%1,%2,%3}, {%4,%5,%6,%7}, {%8,%9}, {%0,%1,%2,%3};"
        : "+f"(c[0]), "+f"(c[1]), "+f"(c[2]), "+f"(c[3])
        : "r"(a0), "r"(a1), "r"(a2), "r"(a3), "r"(b0), "r"(b1));
}

// ---------------- pack adjacency to bits ----------------
// warp w packs ints [w*1024, w*1024+1024) -> 32 words. grid 2048 x 256.
__global__ void pack_adj_kernel(const int* __restrict__ adj) {
    const int warp = blockIdx.x * 8 + (threadIdx.x >> 5);
    const int lane = threadIdx.x & 31;
    const int* src = adj + (size_t)warp * 1024;
    uint32_t mine = 0;
#pragma unroll 4
    for (int u = 0; u < 32; ++u) {
        int v = src[u * 32 + lane];
        uint32_t m = __ballot_sync(0xffffffffu, v != 0);
        if (lane == u) mine = m;
    }
    g_adjp[(size_t)warp * 32 + lane] = mine;
}

// ---------------- proj1: hcat = x @ W_heads (tf32-rounded) + exp factors ----------------
__global__ void proj1_kernel(const float* __restrict__ x,
                             const float* __restrict__ W,
                             const float* __restrict__ a) {
    __shared__ float xs[16][136];
    __shared__ float rs[16][8], rt[16][8];
    const int row0 = blockIdx.x * 16;
    const int tid = threadIdx.x;

#pragma unroll
    for (int u = 0; u < 2; ++u) {
        int idx = tid + u * 256;
        int r = idx >> 5, c = (idx & 31) * 4;
        *(float4*)&xs[r][c] = *(const float4*)&x[(size_t)(row0 + r) * IND + c];
    }
    __syncthreads();

    const int h = tid >> 6, d = tid & 63;
    const float* Wc = W + (size_t)(h * IND) * 64 + d;
    float acc[16];
#pragma unroll
    for (int r = 0; r < 16; ++r) acc[r] = 0.f;
#pragma unroll 4
    for (int i = 0; i < IND; ++i) {
        float wv = Wc[(size_t)i * 64];
#pragma unroll
        for (int r = 0; r < 16; ++r) acc[r] += xs[r][i] * wv;
    }

    const float a1 = a[h * 128 + d];
    const float a2 = a[h * 128 + 64 + d];
    const int warp = tid >> 5, lane = tid & 31;
#pragma unroll
    for (int r = 0; r < 16; ++r) {
        g_hcat[(size_t)(row0 + r) * 256 + tid] = tf32r(acc[r]);
        float sp = warp_sum(acc[r] * a1);
        float tp = warp_sum(acc[r] * a2);
        if (lane == 0) { rs[r][warp] = sp; rt[r][warp] = tp; }
    }
    __syncthreads();
    if ((tid & 63) == 0) {
#pragma unroll
        for (int r = 0; r < 16; ++r) {
            float S = rs[r][2 * h] + rs[r][2 * h + 1];
            float T = rt[r][2 * h] + rt[r][2 * h + 1];
            size_t idx = (size_t)h * (BN * NN) + row0 + r;
            g_Es1[idx] = expf(S);
            g_Fs1[idx] = expf(0.2f * S);
            g_Et1[idx] = expf(T);
            g_Ft1[idx] = expf(0.2f * T);
        }
    }
}

// ---------------- proj2: h2 = att1 @ W_out (tf32-rounded) + exp factors ----------------
__global__ void proj2_kernel(const float* __restrict__ Wout,
                             const float* __restrict__ aout) {
    __shared__ float ys[16][260];
    __shared__ float part[4][16][64];
    __shared__ float rs[16][2], rt[16][2];
    const int row0 = blockIdx.x * 16;
    const int tid = threadIdx.x;

#pragma unroll
    for (int u = 0; u < 4; ++u) {
        int idx = tid + u * 256;
        int r = idx >> 6, c = (idx & 63) * 4;
        *(float4*)&ys[r][c] = *(const float4*)&g_att1[(size_t)(row0 + r) * 256 + c];
    }
    __syncthreads();

    const int p = tid >> 6, d = tid & 63;
    float acc[16];
#pragma unroll
    for (int r = 0; r < 16; ++r) acc[r] = 0.f;
#pragma unroll 4
    for (int i = 0; i < 64; ++i) {
        float wv = Wout[(size_t)(p * 64 + i) * 64 + d];
#pragma unroll
        for (int r = 0; r < 16; ++r) acc[r] += ys[r][p * 64 + i] * wv;
    }
#pragma unroll
    for (int r = 0; r < 16; ++r) part[p][r][d] = acc[r];
    __syncthreads();

    if (p == 0) {
        const float a1 = aout[d], a2 = aout[64 + d];
        const int warp = tid >> 5, lane = tid & 31;
#pragma unroll
        for (int r = 0; r < 16; ++r) {
            float v = part[0][r][d] + part[1][r][d] + part[2][r][d] + part[3][r][d];
            g_h2[(size_t)(row0 + r) * 64 + d] = tf32r(v);
            float sp = warp_sum(v * a1);
            float tp = warp_sum(v * a2);
            if (lane == 0) { rs[r][warp] = sp; rt[r][warp] = tp; }
        }
    }
    __syncthreads();
    if (tid < 16) {
        float S = rs[tid][0] + rs[tid][1];
        float T = rt[tid][0] + rt[tid][1];
        size_t idx = (size_t)(row0 + tid);
        g_Es2[idx] = expf(S);
        g_Fs2[idx] = expf(0.2f * S);
        g_Et2[idx] = expf(T);
        g_Ft2[idx] = expf(0.2f * T);
    }
}

// ---------------- tensor-core (mma.sync tf32) attention ----------------
// CTA: 128 i-rows x 64 dims, K tiled by 32. 256 threads = 8 warps.
// Warp wid computes rows [wid*16, wid*16+16) x all 64 dims.
template <int SPL, int L>
__global__ void __launch_bounds__(256)
attn_m(void) {
    constexpr int HS = (L == 1) ? 256 : 64;
    __shared__ float w_sh[128][36];   // A tile: [i][k], pad 36 -> conflict-free frags
    __shared__ float h_sh[32][68];    // B tile: [k][n], pad 68 -> conflict-free frags
    __shared__ float den_sh[128];

    const int tid = threadIdx.x;
    const int wid = tid >> 5, lane = tid & 31;
    const int lx = lane & 3, ly = lane >> 2;
    const int b = blockIdx.z;
    const int head = (L == 1) ? blockIdx.y : 0;
    const int split = (L == 1) ? 0 : blockIdx.y;
    const int i0 = blockIdx.x * 128;
    const size_t ebase = ((L == 1) ? ((size_t)head * BN + b) : (size_t)b) * NN;

    const float* __restrict__ Es = (L == 1) ? g_Es1 : g_Es2;
    const float* __restrict__ Fs = (L == 1) ? g_Fs1 : g_Fs2;
    const float* __restrict__ Et = (L == 1) ? g_Et1 : g_Et2;
    const float* __restrict__ Ft = (L == 1) ? g_Ft1 : g_Ft2;
    const float* __restrict__ hb = (L == 1) ? (g_hcat + (size_t)b * NN * 256 + head * 64)
                                            : (g_h2 + (size_t)b * NN * 64);
    const uint32_t* __restrict__ adjp = g_adjp + (size_t)b * NN * (NN / 32);

    if (tid < 128) den_sh[tid] = 0.f;

    // ---- w-phase ids: c4 = tid&7 owns 4 j-cols, rw = tid>>3 owns 4 i-rows ----
    const int c4 = tid & 7;
    const int rw = tid >> 3;
    const float4 es4 = *(const float4*)&Es[ebase + i0 + rw * 4];
    const float4 fs4 = *(const float4*)&Fs[ebase + i0 + rw * 4];
    const float esr[4] = {es4.x, es4.y, es4.z, es4.w};
    const float fsr[4] = {fs4.x, fs4.y, fs4.z, fs4.w};
    float denp[4] = {0.f, 0.f, 0.f, 0.f};

    // h staging ids
    const int hj = tid >> 4, hd = (tid & 15) * 4;

    float c_[8][4];
#pragma unroll
    for (int nb = 0; nb < 8; ++nb)
#pragma unroll
        for (int q = 0; q < 4; ++q) c_[nb][q] = 0.f;

    constexpr int KSPAN = NN / SPL;
    constexpr int NT = KSPAN / 32;
    const int jb = split * KSPAN;

    // prefetch registers
    uint32_t pm[4];
    float4 pe, pf, ph0, ph1;
    {
        const int j0 = jb;
#pragma unroll
        for (int k = 0; k < 4; ++k)
            pm[k] = adjp[(size_t)(i0 + rw * 4 + k) * (NN / 32) + (j0 >> 5)];
        pe = *(const float4*)&Et[ebase + j0 + c4 * 4];
        pf = *(const float4*)&Ft[ebase + j0 + c4 * 4];
        ph0 = *(const float4*)&hb[(size_t)(j0 + hj) * HS + hd];
        ph1 = *(const float4*)&hb[(size_t)(j0 + hj + 16) * HS + hd];
    }

    for (int t = 0; t < NT; ++t) {
        if (t) __syncthreads();   // previous tile's fragment LDS complete

        // ---- compute + store w tile ----
        {
            const float e[4] = {pe.x, pe.y, pe.z, pe.w};
            const float f[4] = {pf.x, pf.y, pf.z, pf.w};
#pragma unroll
            for (int k = 0; k < 4; ++k) {
                const uint32_t m = pm[k] >> (c4 * 4);
                float wq[4];
#pragma unroll
                for (int q = 0; q < 4; ++q) {
                    float p = esr[k] * e[q];
                    float w = (p > 1.f) ? p : fsr[k] * f[q];
                    w = ((m >> q) & 1u) ? w : 0.f;
                    denp[k] += w;
                    wq[q] = tf32r(w);
                }
                *(float4*)&w_sh[rw * 4 + k][c4 * 4] = make_float4(wq[0], wq[1], wq[2], wq[3]);
            }
        }
        // ---- store h tile ----
        *(float4*)&h_sh[hj][hd] = ph0;
        *(float4*)&h_sh[hj + 16][hd] = ph1;
        __syncthreads();

        // ---- prefetch next tile ----
        if (t + 1 < NT) {
            const int j0 = jb + (t + 1) * 32;
#pragma unroll
            for (int k = 0; k < 4; ++k)
                pm[k] = adjp[(size_t)(i0 + rw * 4 + k) * (NN / 32) + (j0 >> 5)];
            pe = *(const float4*)&Et[ebase + j0 + c4 * 4];
            pf = *(const float4*)&Ft[ebase + j0 + c4 * 4];
            ph0 = *(const float4*)&hb[(size_t)(j0 + hj) * HS + hd];
            ph1 = *(const float4*)&hb[(size_t)(j0 + hj + 16) * HS + hd];
        }

        // ---- fragment loads + mma ----
        const int r0 = wid * 16 + ly;
#pragma unroll
        for (int kk = 0; kk < 4; ++kk) {
            uint32_t a0 = __float_as_uint(w_sh[r0][kk * 8 + lx]);
            uint32_t a1 = __float_as_uint(w_sh[r0 + 8][kk * 8 + lx]);
            uint32_t a2 = __float_as_uint(w_sh[r0][kk * 8 + lx + 4]);
            uint32_t a3 = __float_as_uint(w_sh[r0 + 8][kk * 8 + lx + 4]);
#pragma unroll
            for (int nb = 0; nb < 8; ++nb) {
                uint32_t b0 = __float_as_uint(h_sh[kk * 8 + lx][nb * 8 + ly]);
                uint32_t b1 = __float_as_uint(h_sh[kk * 8 + lx + 4][nb * 8 + ly]);
                mma_tf32(c_[nb], a0, a1, a2, a3, b0, b1);
            }
        }
    }

    // ---- denominator reduce ----
#pragma unroll
    for (int k = 0; k < 4; ++k) atomicAdd(&den_sh[rw * 4 + k], denp[k]);
    __syncthreads();

    // ---- epilogue ----
    const int r0 = wid * 16 + ly;
    if (L == 1) {
        const float inv0 = 1.0f / den_sh[r0];
        const float inv1 = 1.0f / den_sh[r0 + 8];
        float* o0 = g_att1 + ((size_t)b * NN + i0 + r0) * 256 + head * 64;
        float* o1 = o0 + 8 * 256;
#pragma unroll
        for (int nb = 0; nb < 8; ++nb) {
            const int col = nb * 8 + 2 * lx;
            *(float2*)(o0 + col) = make_float2(c_[nb][0] * inv0, c_[nb][1] * inv0);
            *(float2*)(o1 + col) = make_float2(c_[nb][2] * inv1, c_[nb][3] * inv1);
        }
    } else {
        float* nb_ = g_num2 + ((size_t)split * BN + b) * NN * 64;
        float* o0 = nb_ + (size_t)(i0 + r0) * 64;
        float* o1 = o0 + 8 * 64;
#pragma unroll
        for (int nb = 0; nb < 8; ++nb) {
            const int col = nb * 8 + 2 * lx;
            *(float2*)(o0 + col) = make_float2(c_[nb][0], c_[nb][1]);
            *(float2*)(o1 + col) = make_float2(c_[nb][2], c_[nb][3]);
        }
        if (tid < 128)
            g_den2[((size_t)split * BN + b) * NN + i0 + tid] = den_sh[tid];
    }
}

// ---------------- layer-2 split-K combine ----------------
__global__ void combine2_kernel(float* __restrict__ out) {
    size_t idx = (size_t)blockIdx.x * 256 + threadIdx.x;  // BN*NN*16 float4 groups
    size_t row = idx >> 4;
    int c = (int)(idx & 15) * 4;
    float den = 0.f;
    float4 n = make_float4(0.f, 0.f, 0.f, 0.f);
#pragma unroll
    for (int s = 0; s < 4; ++s) {
        den += g_den2[(size_t)s * BN * NN + row];
        float4 p = *(const float4*)&g_num2[((size_t)s * BN * NN + row) * 64 + c];
        n.x += p.x; n.y += p.y; n.z += p.z; n.w += p.w;
    }
    float inv = 1.0f / den;
    *(float4*)&out[row * 64 + c] = make_float4(n.x * inv, n.y * inv, n.z * inv, n.w * inv);
}

extern "C" void kernel_launch(void* const* d_in, const int* in_sizes, int n_in,
                              void* d_out, int out_size) {
    const float* x   = (const float*)d_in[0];
    const int*   adj = (const int*)  d_in[1];
    const float* Wh  = (const float*)d_in[2];
    const float* ah  = (const float*)d_in[3];
    const float* Wo  = (const float*)d_in[4];
    const float* ao  = (const float*)d_in[5];
    float* out = (float*)d_out;

    pack_adj_kernel<<<2048, 256>>>(adj);
    proj1_kernel<<<BN * NN / 16, 256>>>(x, Wh, ah);
    attn_m<1, 1><<<dim3(NN / 128, NHEADS, BN), 256>>>();
    proj2_kernel<<<BN * NN / 16, 256>>>(Wo, ao);
    attn_m<4, 2><<<dim3(NN / 128, 4, BN), 256>>>();
    combine2_kernel<<<BN * NN * 16 / 256, 256>>>(out);
}

// round 5
// speedup vs baseline: 7.9591x; 1.3475x over previous
#include <cuda_runtime.h>
#include <cstdint>

#define BN 4
#define NN 2048
#define IND 128
#define NHEADS 4

// ---------------- scratch ----------------
__device__ float g_hcat[(size_t)BN * NN * 256];     // layer-1 h (tf32-rounded), [b][n][h*64+d]
__device__ float g_att1[(size_t)BN * NN * 256];     // layer-1 attention out (fp32)
__device__ float g_h2[(size_t)BN * NN * 64];        // layer-2 h (tf32-rounded)
__device__ float g_num2[(size_t)4 * BN * NN * 64];  // layer-2 split-K numerators
__device__ float g_den2[(size_t)4 * BN * NN];
__device__ uint32_t g_adjp[(size_t)BN * 64 * NN];   // bit-packed adjacency, TRANSPOSED [b][jword][i]

__device__ float g_Es1[NHEADS * BN * NN];
__device__ float g_Fs1[NHEADS * BN * NN];
__device__ float g_Et1[NHEADS * BN * NN];
__device__ float g_Ft1[NHEADS * BN * NN];
__device__ float g_Es2[BN * NN];
__device__ float g_Fs2[BN * NN];
__device__ float g_Et2[BN * NN];
__device__ float g_Ft2[BN * NN];

__device__ __forceinline__ float tf32r(float x) {
    uint32_t v;
    asm("cvt.rna.tf32.f32 %0, %1;" : "=r"(v) : "f"(x));
    return __uint_as_float(v);
}
__device__ __forceinline__ float warp_sum(float v) {
#pragma unroll
    for (int o = 16; o > 0; o >>= 1) v += __shfl_xor_sync(0xffffffffu, v, o);
    return v;
}
__device__ __forceinline__ void mma_tf32(float* c, uint32_t a0, uint32_t a1, uint32_t a2,
                                         uint32_t a3, uint32_t b0, uint32_t b1) {
    asm volatile(
        "mma.sync.aligned.m16n8k8.row.col.f32.tf32.tf32.f32 "
        "{%0,%1,%2,%3}, {%4,%5,%6,%7}, {%8,%9}, {%0,%1,%2,%3};"
        : "+f"(c[0]), "+f"(c[1]), "+f"(c[2]), "+f"(c[3])
        : "r"(a0), "r"(a1), "r"(a2), "r"(a3), "r"(b0), "r"(b1));
}

// ---------------- pack adjacency to bits, transposed [b][jword][i] ----------------
// warp w handles row i = (w>>1)&2047, batch b = w>>12, j-half = w&1 (1024 j -> 32 words).
__global__ void pack_adj_kernel(const int* __restrict__ adj) {
    const int w = blockIdx.x * 8 + (threadIdx.x >> 5);
    const int lane = threadIdx.x & 31;
    const int b = w >> 12;
    const int i = (w >> 1) & (NN - 1);
    const int half = w & 1;
    const int* src = adj + (size_t)w * 1024;
    uint32_t mine = 0;
#pragma unroll 4
    for (int u = 0; u < 32; ++u) {
        int v = src[u * 32 + lane];
        uint32_t m = __ballot_sync(0xffffffffu, v != 0);
        if (lane == u) mine = m;
    }
    g_adjp[((size_t)b * 64 + half * 32 + lane) * NN + i] = mine;
}

// ---------------- proj1: hcat = x @ W_heads (tf32-rounded) + exp factors ----------------
__global__ void proj1_kernel(const float* __restrict__ x,
                             const float* __restrict__ W,
                             const float* __restrict__ a) {
    __shared__ float xs[16][136];
    __shared__ float rs[16][8], rt[16][8];
    const int row0 = blockIdx.x * 16;
    const int tid = threadIdx.x;

#pragma unroll
    for (int u = 0; u < 2; ++u) {
        int idx = tid + u * 256;
        int r = idx >> 5, c = (idx & 31) * 4;
        *(float4*)&xs[r][c] = *(const float4*)&x[(size_t)(row0 + r) * IND + c];
    }
    __syncthreads();

    const int h = tid >> 6, d = tid & 63;
    const float* Wc = W + (size_t)(h * IND) * 64 + d;
    float acc[16];
#pragma unroll
    for (int r = 0; r < 16; ++r) acc[r] = 0.f;
#pragma unroll 2
    for (int i = 0; i < IND; i += 4) {
        float w0 = Wc[(size_t)(i + 0) * 64];
        float w1 = Wc[(size_t)(i + 1) * 64];
        float w2 = Wc[(size_t)(i + 2) * 64];
        float w3 = Wc[(size_t)(i + 3) * 64];
#pragma unroll
        for (int r = 0; r < 16; ++r) {
            float4 xv = *(const float4*)&xs[r][i];
            acc[r] += xv.x * w0 + xv.y * w1 + xv.z * w2 + xv.w * w3;
        }
    }

    const float a1 = a[h * 128 + d];
    const float a2 = a[h * 128 + 64 + d];
    const int warp = tid >> 5, lane = tid & 31;
#pragma unroll
    for (int r = 0; r < 16; ++r) {
        g_hcat[(size_t)(row0 + r) * 256 + tid] = tf32r(acc[r]);
        float sp = warp_sum(acc[r] * a1);
        float tp = warp_sum(acc[r] * a2);
        if (lane == 0) { rs[r][warp] = sp; rt[r][warp] = tp; }
    }
    __syncthreads();
    if ((tid & 63) == 0) {
#pragma unroll
        for (int r = 0; r < 16; ++r) {
            float S = rs[r][2 * h] + rs[r][2 * h + 1];
            float T = rt[r][2 * h] + rt[r][2 * h + 1];
            size_t idx = (size_t)h * (BN * NN) + row0 + r;
            g_Es1[idx] = expf(S);
            g_Fs1[idx] = expf(0.2f * S);
            g_Et1[idx] = expf(T);
            g_Ft1[idx] = expf(0.2f * T);
        }
    }
}

// ---------------- proj2: h2 = att1 @ W_out (tf32-rounded) + exp factors ----------------
__global__ void proj2_kernel(const float* __restrict__ Wout,
                             const float* __restrict__ aout) {
    __shared__ float ys[16][260];
    __shared__ float part[4][16][64];
    __shared__ float rs[16][2], rt[16][2];
    const int row0 = blockIdx.x * 16;
    const int tid = threadIdx.x;

#pragma unroll
    for (int u = 0; u < 4; ++u) {
        int idx = tid + u * 256;
        int r = idx >> 6, c = (idx & 63) * 4;
        *(float4*)&ys[r][c] = *(const float4*)&g_att1[(size_t)(row0 + r) * 256 + c];
    }
    __syncthreads();

    const int p = tid >> 6, d = tid & 63;
    float acc[16];
#pragma unroll
    for (int r = 0; r < 16; ++r) acc[r] = 0.f;
#pragma unroll 2
    for (int i = 0; i < 64; i += 4) {
        float w0 = Wout[(size_t)(p * 64 + i + 0) * 64 + d];
        float w1 = Wout[(size_t)(p * 64 + i + 1) * 64 + d];
        float w2 = Wout[(size_t)(p * 64 + i + 2) * 64 + d];
        float w3 = Wout[(size_t)(p * 64 + i + 3) * 64 + d];
#pragma unroll
        for (int r = 0; r < 16; ++r) {
            float4 yv = *(const float4*)&ys[r][p * 64 + i];
            acc[r] += yv.x * w0 + yv.y * w1 + yv.z * w2 + yv.w * w3;
        }
    }
#pragma unroll
    for (int r = 0; r < 16; ++r) part[p][r][d] = acc[r];
    __syncthreads();

    if (p == 0) {
        const float a1 = aout[d], a2 = aout[64 + d];
        const int warp = tid >> 5, lane = tid & 31;
#pragma unroll
        for (int r = 0; r < 16; ++r) {
            float v = part[0][r][d] + part[1][r][d] + part[2][r][d] + part[3][r][d];
            g_h2[(size_t)(row0 + r) * 64 + d] = tf32r(v);
            float sp = warp_sum(v * a1);
            float tp = warp_sum(v * a2);
            if (lane == 0) { rs[r][warp] = sp; rt[r][warp] = tp; }
        }
    }
    __syncthreads();
    if (tid < 16) {
        float S = rs[tid][0] + rs[tid][1];
        float T = rt[tid][0] + rt[tid][1];
        size_t idx = (size_t)(row0 + tid);
        g_Es2[idx] = expf(S);
        g_Fs2[idx] = expf(0.2f * S);
        g_Et2[idx] = expf(T);
        g_Ft2[idx] = expf(0.2f * T);
    }
}

// ---------------- tensor-core (mma.sync tf32) attention, K-split warps ----------------
// CTA: 128 i-rows x 64 dims, K tiled by 32. 8 warps = 4 row-groups(32 rows) x 2 K-halves(16 k).
template <int SPL, int L>
__global__ void __launch_bounds__(256, 2)
attn_m(void) {
    constexpr int HS = (L == 1) ? 256 : 64;
    __shared__ float w_sh[128][36];   // A tile [i][k] (frag-read conflict-free)
    __shared__ float h_sh[32][72];    // B tile [k][n] (pad 72 -> frag-read conflict-free)
    __shared__ float den_sh[128];

    const int tid = threadIdx.x;
    const int wid = tid >> 5, lane = tid & 31;
    const int lx = lane & 3, ly = lane >> 2;
    const int wg = wid >> 1;   // row group: rows [wg*32, wg*32+32)
    const int kg = wid & 1;    // K half: k in [kg*16, kg*16+16)
    const int b = blockIdx.z;
    const int head = (L == 1) ? blockIdx.y : 0;
    const int split = (L == 1) ? 0 : blockIdx.y;
    const int i0 = blockIdx.x * 128;
    const size_t ebase = ((L == 1) ? ((size_t)head * BN + b) : (size_t)b) * NN;

    const float* __restrict__ Es = (L == 1) ? g_Es1 : g_Es2;
    const float* __restrict__ Fs = (L == 1) ? g_Fs1 : g_Fs2;
    const float* __restrict__ Et = (L == 1) ? g_Et1 : g_Et2;
    const float* __restrict__ Ft = (L == 1) ? g_Ft1 : g_Ft2;
    const float* __restrict__ hb = (L == 1) ? (g_hcat + (size_t)b * NN * 256 + head * 64)
                                            : (g_h2 + (size_t)b * NN * 64);
    const uint32_t* __restrict__ adjpT = g_adjp + (size_t)b * 64 * NN;

    if (tid < 128) den_sh[tid] = 0.f;

    // w-phase ids: c4 = tid&7 owns 4 j-cols, rw = tid>>3 owns 4 i-rows
    const int c4 = tid & 7;
    const int rw = tid >> 3;
    const float4 es4 = *(const float4*)&Es[ebase + i0 + rw * 4];
    const float4 fs4 = *(const float4*)&Fs[ebase + i0 + rw * 4];
    const float esr[4] = {es4.x, es4.y, es4.z, es4.w};
    const float fsr[4] = {fs4.x, fs4.y, fs4.z, fs4.w};
    float denp[4] = {0.f, 0.f, 0.f, 0.f};

    // h staging ids
    const int hj = tid >> 4, hd = (tid & 15) * 4;

    float4 c_[2][8];   // [row-block][n-block]
#pragma unroll
    for (int rb = 0; rb < 2; ++rb)
#pragma unroll
        for (int nb = 0; nb < 8; ++nb) c_[rb][nb] = make_float4(0.f, 0.f, 0.f, 0.f);

    constexpr int KSPAN = NN / SPL;
    constexpr int NT = KSPAN / 32;
    const int jb = split * KSPAN;

    // prefetch registers
    int4 pm;
    float4 pe, pf, ph0, ph1;
    {
        const int j0 = jb;
        pm = *(const int4*)&adjpT[(size_t)(j0 >> 5) * NN + i0 + rw * 4];
        pe = *(const float4*)&Et[ebase + j0 + c4 * 4];
        pf = *(const float4*)&Ft[ebase + j0 + c4 * 4];
        ph0 = *(const float4*)&hb[(size_t)(j0 + hj) * HS + hd];
        ph1 = *(const float4*)&hb[(size_t)(j0 + hj + 16) * HS + hd];
    }

    for (int t = 0; t < NT; ++t) {
        if (t) __syncthreads();   // previous tile's fragment LDS complete

        // ---- compute + store w tile (raw fp32; HMMA truncates to tf32) ----
        {
            const float e[4] = {pe.x, pe.y, pe.z, pe.w};
            const float f[4] = {pf.x, pf.y, pf.z, pf.w};
            const uint32_t mw[4] = {(uint32_t)pm.x, (uint32_t)pm.y,
                                    (uint32_t)pm.z, (uint32_t)pm.w};
#pragma unroll
            for (int k = 0; k < 4; ++k) {
                const uint32_t m = mw[k] >> (c4 * 4);
                float wq[4];
#pragma unroll
                for (int q = 0; q < 4; ++q) {
                    float p = esr[k] * e[q];
                    float w = (p > 1.f) ? p : fsr[k] * f[q];
                    w = ((m >> q) & 1u) ? w : 0.f;
                    denp[k] += w;
                    wq[q] = w;
                }
                *(float4*)&w_sh[rw * 4 + k][c4 * 4] = make_float4(wq[0], wq[1], wq[2], wq[3]);
            }
        }
        // ---- store h tile ----
        *(float4*)&h_sh[hj][hd] = ph0;
        *(float4*)&h_sh[hj + 16][hd] = ph1;
        __syncthreads();

        // ---- prefetch next tile ----
        if (t + 1 < NT) {
            const int j0 = jb + (t + 1) * 32;
            pm = *(const int4*)&adjpT[(size_t)(j0 >> 5) * NN + i0 + rw * 4];
            pe = *(const float4*)&Et[ebase + j0 + c4 * 4];
            pf = *(const float4*)&Ft[ebase + j0 + c4 * 4];
            ph0 = *(const float4*)&hb[(size_t)(j0 + hj) * HS + hd];
            ph1 = *(const float4*)&hb[(size_t)(j0 + hj + 16) * HS + hd];
        }

        // ---- fragment loads + mma (this warp's K half only) ----
        const int r0 = wg * 32 + ly;
#pragma unroll
        for (int kk2 = 0; kk2 < 2; ++kk2) {
            const int kc = (kg * 2 + kk2) * 8;
            uint32_t a[2][4];
#pragma unroll
            for (int rb = 0; rb < 2; ++rb) {
                a[rb][0] = __float_as_uint(w_sh[r0 + rb * 16][kc + lx]);
                a[rb][1] = __float_as_uint(w_sh[r0 + rb * 16 + 8][kc + lx]);
                a[rb][2] = __float_as_uint(w_sh[r0 + rb * 16][kc + lx + 4]);
                a[rb][3] = __float_as_uint(w_sh[r0 + rb * 16 + 8][kc + lx + 4]);
            }
#pragma unroll
            for (int nb = 0; nb < 8; ++nb) {
                uint32_t b0 = __float_as_uint(h_sh[kc + lx][nb * 8 + ly]);
                uint32_t b1 = __float_as_uint(h_sh[kc + lx + 4][nb * 8 + ly]);
                mma_tf32((float*)&c_[0][nb], a[0][0], a[0][1], a[0][2], a[0][3], b0, b1);
                mma_tf32((float*)&c_[1][nb], a[1][0], a[1][1], a[1][2], a[1][3], b0, b1);
            }
        }
    }

    // ---- denominator reduce ----
#pragma unroll
    for (int k = 0; k < 4; ++k) atomicAdd(&den_sh[rw * 4 + k], denp[k]);

    // ---- merge K-half partial sums (kg=1 -> kg=0) via w_sh as scratch ----
    float* mbuf = &w_sh[0][0];   // 4608 floats >= 4096 needed
#pragma unroll
    for (int half = 0; half < 2; ++half) {
        __syncthreads();
        if (kg == 1) {
            float4* p = (float4*)(mbuf + (wg * 32 + lane) * 32);
#pragma unroll
            for (int rb = 0; rb < 2; ++rb)
#pragma unroll
                for (int nn = 0; nn < 4; ++nn) p[rb * 4 + nn] = c_[rb][half * 4 + nn];
        }
        __syncthreads();
        if (kg == 0) {
            const float4* p = (const float4*)(mbuf + (wg * 32 + lane) * 32);
#pragma unroll
            for (int rb = 0; rb < 2; ++rb)
#pragma unroll
                for (int nn = 0; nn < 4; ++nn) {
                    float4 v = p[rb * 4 + nn];
                    c_[rb][half * 4 + nn].x += v.x;
                    c_[rb][half * 4 + nn].y += v.y;
                    c_[rb][half * 4 + nn].z += v.z;
                    c_[rb][half * 4 + nn].w += v.w;
                }
        }
    }
    __syncthreads();

    // ---- epilogue (kg==0 warps own the merged sums) ----
    if (kg == 0) {
#pragma unroll
        for (int rb = 0; rb < 2; ++rb) {
            const int r0 = wg * 32 + rb * 16 + ly;
            if (L == 1) {
                const float inv0 = 1.0f / den_sh[r0];
                const float inv1 = 1.0f / den_sh[r0 + 8];
                float* o0 = g_att1 + ((size_t)b * NN + i0 + r0) * 256 + head * 64;
                float* o1 = o0 + 8 * 256;
#pragma unroll
                for (int nb = 0; nb < 8; ++nb) {
                    const int col = nb * 8 + 2 * lx;
                    *(float2*)(o0 + col) = make_float2(c_[rb][nb].x * inv0, c_[rb][nb].y * inv0);
                    *(float2*)(o1 + col) = make_float2(c_[rb][nb].z * inv1, c_[rb][nb].w * inv1);
                }
            } else {
                float* nbase = g_num2 + ((size_t)split * BN + b) * NN * 64;
                float* o0 = nbase + (size_t)(i0 + r0) * 64;
                float* o1 = o0 + 8 * 64;
#pragma unroll
                for (int nb = 0; nb < 8; ++nb) {
                    const int col = nb * 8 + 2 * lx;
                    *(float2*)(o0 + col) = make_float2(c_[rb][nb].x, c_[rb][nb].y);
                    *(float2*)(o1 + col) = make_float2(c_[rb][nb].z, c_[rb][nb].w);
                }
            }
        }
    }
    if (L == 2 && tid < 128)
        g_den2[((size_t)split * BN + b) * NN + i0 + tid] = den_sh[tid];
}

// ---------------- layer-2 split-K combine ----------------
__global__ void combine2_kernel(float* __restrict__ out) {
    size_t idx = (size_t)blockIdx.x * 256 + threadIdx.x;
    size_t row = idx >> 4;
    int c = (int)(idx & 15) * 4;
    float den = 0.f;
    float4 n = make_float4(0.f, 0.f, 0.f, 0.f);
#pragma unroll
    for (int s = 0; s < 4; ++s) {
        den += g_den2[(size_t)s * BN * NN + row];
        float4 p = *(const float4*)&g_num2[((size_t)s * BN * NN + row) * 64 + c];
        n.x += p.x; n.y += p.y; n.z += p.z; n.w += p.w;
    }
    float inv = 1.0f / den;
    *(float4*)&out[row * 64 + c] = make_float4(n.x * inv, n.y * inv, n.z * inv, n.w * inv);
}

extern "C" void kernel_launch(void* const* d_in, const int* in_sizes, int n_in,
                              void* d_out, int out_size) {
    const float* x   = (const float*)d_in[0];
    const int*   adj = (const int*)  d_in[1];
    const float* Wh  = (const float*)d_in[2];
    const float* ah  = (const float*)d_in[3];
    const float* Wo  = (const float*)d_in[4];
    const float* ao  = (const float*)d_in[5];
    float* out = (float*)d_out;

    pack_adj_kernel<<<2048, 256>>>(adj);
    proj1_kernel<<<BN * NN / 16, 256>>>(x, Wh, ah);
    attn_m<1, 1><<<dim3(NN / 128, NHEADS, BN), 256>>>();
    proj2_kernel<<<BN * NN / 16, 256>>>(Wo, ao);
    attn_m<4, 2><<<dim3(NN / 128, 4, BN), 256>>>();
    combine2_kernel<<<BN * NN * 16 / 256, 256>>>(out);
}